// round 9
// baseline (speedup 1.0000x reference)
#include <cuda_runtime.h>

// SSIM loss, pred/target [16,3,512,512] f32.
// Separable 11-tap Gaussian; fields packed 2-wide for fma.rn.f32x2:
//   stream A: (p, t)      packed in .x/.y
//   stream B: (p*p, t*t)  packed
//   stream C: p*t packed across row-pairs (r, r+21)
// Fused tile kernel (64x32 out, 74x42 loaded) + deterministic reduce.

#define TX   64
#define TY   32
#define LX   74
#define LY   42
#define SPW  75      // spt row stride (u64 units); lane-row delta 150 words -> conflict-free halves
#define CS   43      // shA/shB column stride (u64); lane-col delta 86 words -> conflict-free halves
#define CSS  45      // shC column stride (f32); delta 45 words (odd) -> conflict-free
#define GX   (512/TX)
#define GY   (512/TY)
#define GZ   48
#define NBLK (GX*GY*GZ)
#define NTOT 12582912.0

using u64 = unsigned long long;

__host__ __device__ constexpr float GWc(int k) {
    return (k == 0) ? 0.00102838f
         : (k == 1) ? 0.00759875f
         : (k == 2) ? 0.03600077f
         : (k == 3) ? 0.10936070f
         : (k == 4) ? 0.21300553f
         : (k == 5) ? 0.26601172f
         : (k == 6) ? 0.21300553f
         : (k == 7) ? 0.10936070f
         : (k == 8) ? 0.03600077f
         : (k == 9) ? 0.00759875f
         :            0.00102838f;
}

__device__ __forceinline__ u64 pack2(float lo, float hi) {
    u64 r; asm("mov.b64 %0, {%1,%2};" : "=l"(r) : "f"(lo), "f"(hi)); return r;
}
__device__ __forceinline__ void unpack2(u64 v, float& lo, float& hi) {
    asm("mov.b64 {%0,%1}, %2;" : "=f"(lo), "=f"(hi) : "l"(v));
}
__device__ __forceinline__ u64 fma2(u64 a, u64 b, u64 c) {
    u64 r; asm("fma.rn.f32x2 %0, %1, %2, %3;" : "=l"(r) : "l"(a), "l"(b), "l"(c)); return r;
}
__device__ __forceinline__ u64 mul2(u64 a, u64 b) {
    u64 r; asm("mul.rn.f32x2 %0, %1, %2;" : "=l"(r) : "l"(a), "l"(b)); return r;
}

__device__ float g_partials[NBLK];

__global__ void __launch_bounds__(256, 2)
ssim_tile_kernel(const float* __restrict__ pred, const float* __restrict__ targ)
{
    extern __shared__ char smem_raw[];
    u64*   spt  = (u64*)smem_raw;              // LY*SPW  (p,t) pairs
    u64*   shA  = spt + LY * SPW;              // 64*CS   hpass (mu1h, mu2h), [col][row]
    u64*   shB  = shA + 64 * CS;               // 64*CS   hpass (p2h, t2h),  [col][row]
    float* shC  = (float*)(shB + 64 * CS);     // 64*CSS  hpass pt, [col][row]
    float* sred = shC + 64 * CSS;              // 8 floats, reduction scratch

    const int tid = threadIdx.x;
    const int x0 = blockIdx.x * TX;
    const int y0 = blockIdx.y * TY;
    const int plane = blockIdx.z * (512 * 512);
    const float* pb = pred + plane;
    const float* tb = targ + plane;

    // ---- Load tile with halo, interleave (p,t) into u64 ----
    for (int i = tid; i < LY * LX; i += 256) {
        int r = i / LX;
        int c = i - r * LX;
        int gy = y0 - 5 + r;
        int gx = x0 - 5 + c;
        bool ok = ((unsigned)gy < 512u) && ((unsigned)gx < 512u);
        float pv = ok ? __ldg(pb + gy * 512 + gx) : 0.0f;
        float tv = ok ? __ldg(tb + gy * 512 + gx) : 0.0f;
        spt[r * SPW + c] = pack2(pv, tv);
    }
    __syncthreads();

    // packed weights (duplicated lanes); symmetric -> compiler CSEs to 6 live regs
    u64 wp[11];
    #pragma unroll
    for (int k = 0; k < 11; k++) wp[k] = pack2(GWc(k), GWc(k));

    // ---- Horizontal pass, warp-pure stream assignment ----
    // warps 0-2: stream A (84 tasks)   warps 3-5: stream B (84 tasks)
    // warps 6-7: stream C (42 tasks, row-pairs)
    const int w = tid >> 5;
    if (w < 3) {
        int t = tid;
        if (t < 84) {
            int half = (t >= 42); int r = t - half * 42; int cb = half * 32;
            const u64* row = spt + r * SPW + cb;
            u64 acc[32];
            #pragma unroll
            for (int o = 0; o < 32; o++) acc[o] = 0ull;
            #pragma unroll
            for (int j = 0; j < 42; j++) {
                u64 x = row[j];
                #pragma unroll
                for (int k = 0; k < 11; k++) {
                    int o = j - k;
                    if (o >= 0 && o < 32) acc[o] = fma2(wp[k], x, acc[o]);
                }
            }
            u64* out = shA + r;
            #pragma unroll
            for (int o = 0; o < 32; o++) out[(cb + o) * CS] = acc[o];
        }
    } else if (w < 6) {
        int t = tid - 96;
        if (t < 84) {
            int half = (t >= 42); int r = t - half * 42; int cb = half * 32;
            const u64* row = spt + r * SPW + cb;
            u64 acc[32];
            #pragma unroll
            for (int o = 0; o < 32; o++) acc[o] = 0ull;
            #pragma unroll
            for (int j = 0; j < 42; j++) {
                u64 x = row[j];
                x = mul2(x, x);
                #pragma unroll
                for (int k = 0; k < 11; k++) {
                    int o = j - k;
                    if (o >= 0 && o < 32) acc[o] = fma2(wp[k], x, acc[o]);
                }
            }
            u64* out = shB + r;
            #pragma unroll
            for (int o = 0; o < 32; o++) out[(cb + o) * CS] = acc[o];
        }
    } else {
        int t = tid - 192;
        if (t < 42) {
            int half = (t >= 21); int rp = t - half * 21; int cb = half * 32;
            int r0 = rp, r1 = rp + 21;
            const u64* rowa = spt + r0 * SPW + cb;
            const u64* rowb = spt + r1 * SPW + cb;
            u64 acc[32];
            #pragma unroll
            for (int o = 0; o < 32; o++) acc[o] = 0ull;
            #pragma unroll
            for (int j = 0; j < 42; j++) {
                float pa, ta, pc, tc;
                unpack2(rowa[j], pa, ta);
                unpack2(rowb[j], pc, tc);
                u64 x = pack2(pa * ta, pc * tc);
                #pragma unroll
                for (int k = 0; k < 11; k++) {
                    int o = j - k;
                    if (o >= 0 && o < 32) acc[o] = fma2(wp[k], x, acc[o]);
                }
            }
            #pragma unroll
            for (int o = 0; o < 32; o++) {
                float va, vb;
                unpack2(acc[o], va, vb);
                shC[(cb + o) * CSS + r0] = va;
                shC[(cb + o) * CSS + r1] = vb;
            }
        }
    }
    __syncthreads();

    // ---- Vertical pass + SSIM: thread = (column x, 8-row strip) ----
    const int x  = tid & 63;
    const int r0 = (tid >> 6) * 8;

    u64 mu[8];
    {
        const u64* col = shA + x * CS + r0;
        u64 wv[18];
        #pragma unroll
        for (int j = 0; j < 18; j++) wv[j] = col[j];
        #pragma unroll
        for (int o = 0; o < 8; o++) {
            u64 a = mul2(wp[0], wv[o]);
            #pragma unroll
            for (int k = 1; k < 11; k++) a = fma2(wp[k], wv[o + k], a);
            mu[o] = a;
        }
    }
    u64 sq[8];
    {
        const u64* col = shB + x * CS + r0;
        u64 wv[18];
        #pragma unroll
        for (int j = 0; j < 18; j++) wv[j] = col[j];
        #pragma unroll
        for (int o = 0; o < 8; o++) {
            u64 a = mul2(wp[0], wv[o]);
            #pragma unroll
            for (int k = 1; k < 11; k++) a = fma2(wp[k], wv[o + k], a);
            sq[o] = a;
        }
    }
    float cpt[8];
    {
        const float* col = shC + x * CSS + r0;
        float wc[18];
        #pragma unroll
        for (int j = 0; j < 18; j++) wc[j] = col[j];
        u64 pw[14];
        #pragma unroll
        for (int j = 0; j < 14; j++) pw[j] = pack2(wc[j], wc[j + 4]);
        #pragma unroll
        for (int o = 0; o < 4; o++) {
            u64 a = mul2(wp[0], pw[o]);
            #pragma unroll
            for (int k = 1; k < 11; k++) a = fma2(wp[k], pw[o + k], a);
            unpack2(a, cpt[o], cpt[o + 4]);   // outputs o and o+4
        }
    }

    const float C1 = 0.0001f;
    const float C2 = 0.0009f;
    float lsum = 0.0f;
    #pragma unroll
    for (int o = 0; o < 8; o++) {
        float mu1, mu2, ep2, et2;
        unpack2(mu[o], mu1, mu2);
        unpack2(sq[o], ep2, et2);
        float mu1sq = mu1 * mu1;
        float mu2sq = mu2 * mu2;
        float mu12  = mu1 * mu2;
        float s1  = ep2 - mu1sq;
        float s2  = et2 - mu2sq;
        float s12 = cpt[o] - mu12;
        float num = (2.0f * mu12 + C1) * (2.0f * s12 + C2);
        float den = (mu1sq + mu2sq + C1) * (s1 + s2 + C2);
        lsum += __fdividef(num, den);
    }

    // ---- Deterministic block reduction ----
    #pragma unroll
    for (int off = 16; off > 0; off >>= 1)
        lsum += __shfl_down_sync(0xffffffffu, lsum, off);
    if ((tid & 31) == 0) sred[tid >> 5] = lsum;
    __syncthreads();
    if (tid == 0) {
        float tot = 0.0f;
        #pragma unroll
        for (int wi = 0; wi < 8; wi++) tot += sred[wi];
        int bidx = (blockIdx.z * gridDim.y + blockIdx.y) * gridDim.x + blockIdx.x;
        g_partials[bidx] = tot;
    }
}

__global__ void __launch_bounds__(1024, 1)
ssim_finalize(float* __restrict__ out)
{
    __shared__ double shr[32];
    const int tid = threadIdx.x;
    double s = 0.0;
    for (int i = tid; i < NBLK; i += 1024)
        s += (double)g_partials[i];
    #pragma unroll
    for (int off = 16; off > 0; off >>= 1)
        s += __shfl_down_sync(0xffffffffu, s, off);
    if ((tid & 31) == 0) shr[tid >> 5] = s;
    __syncthreads();
    if (tid == 0) {
        double tot = 0.0;
        #pragma unroll
        for (int w = 0; w < 32; w++) tot += shr[w];
        out[0] = (float)(1.0 - tot / NTOT);
    }
}

extern "C" void kernel_launch(void* const* d_in, const int* in_sizes, int n_in,
                              void* d_out, int out_size)
{
    const float* pred = (const float*)d_in[0];
    const float* targ = (const float*)d_in[1];
    float* out = (float*)d_out;

    constexpr int smem_bytes =
        (LY * SPW + 2 * 64 * CS) * 8 + 64 * CSS * 4 + 8 * 4;
    cudaFuncSetAttribute(ssim_tile_kernel,
                         cudaFuncAttributeMaxDynamicSharedMemorySize, smem_bytes);

    dim3 grid(GX, GY, GZ);
    ssim_tile_kernel<<<grid, 256, smem_bytes>>>(pred, targ);
    ssim_finalize<<<1, 1024>>>(out);
}

// round 10
// speedup vs baseline: 1.0010x; 1.0010x over previous
#include <cuda_runtime.h>

// SSIM loss, pred/target [16,3,512,512] f32.
// Separable 11-tap Gaussian; fields packed 2-wide for fma.rn.f32x2:
//   stream A: (p, t)      packed in .x/.y
//   stream B: (p*p, t*t)  packed
//   stream C: p*t packed across row-pairs (r, r+21)
// Fused tile kernel (64x32 out, 74x42 loaded) + deterministic reduce.

#define TX   64
#define TY   32
#define LX   74
#define LY   42
#define SPW  75      // spt row stride (u64 units); lane-row delta 150 words -> conflict-free halves
#define CS   43      // shA/shB column stride (u64); lane-col delta 86 words -> conflict-free halves
#define CSS  45      // shC column stride (f32); delta 45 words (odd) -> conflict-free
#define GX   (512/TX)
#define GY   (512/TY)
#define GZ   48
#define NBLK (GX*GY*GZ)
#define NTOT 12582912.0

using u64 = unsigned long long;

__host__ __device__ constexpr float GWc(int k) {
    return (k == 0) ? 0.00102838f
         : (k == 1) ? 0.00759875f
         : (k == 2) ? 0.03600077f
         : (k == 3) ? 0.10936070f
         : (k == 4) ? 0.21300553f
         : (k == 5) ? 0.26601172f
         : (k == 6) ? 0.21300553f
         : (k == 7) ? 0.10936070f
         : (k == 8) ? 0.03600077f
         : (k == 9) ? 0.00759875f
         :            0.00102838f;
}

__device__ __forceinline__ u64 pack2(float lo, float hi) {
    u64 r; asm("mov.b64 %0, {%1,%2};" : "=l"(r) : "f"(lo), "f"(hi)); return r;
}
__device__ __forceinline__ void unpack2(u64 v, float& lo, float& hi) {
    asm("mov.b64 {%0,%1}, %2;" : "=f"(lo), "=f"(hi) : "l"(v));
}
__device__ __forceinline__ u64 fma2(u64 a, u64 b, u64 c) {
    u64 r; asm("fma.rn.f32x2 %0, %1, %2, %3;" : "=l"(r) : "l"(a), "l"(b), "l"(c)); return r;
}
__device__ __forceinline__ u64 mul2(u64 a, u64 b) {
    u64 r; asm("mul.rn.f32x2 %0, %1, %2;" : "=l"(r) : "l"(a), "l"(b)); return r;
}

__device__ float g_partials[NBLK];

__global__ void __launch_bounds__(256, 2)
ssim_tile_kernel(const float* __restrict__ pred, const float* __restrict__ targ)
{
    extern __shared__ char smem_raw[];
    u64*   spt  = (u64*)smem_raw;              // LY*SPW  (p,t) pairs
    u64*   shA  = spt + LY * SPW;              // 64*CS   hpass (mu1h, mu2h), [col][row]
    u64*   shB  = shA + 64 * CS;               // 64*CS   hpass (p2h, t2h),  [col][row]
    float* shC  = (float*)(shB + 64 * CS);     // 64*CSS  hpass pt, [col][row]
    float* sred = shC + 64 * CSS;              // 8 floats, reduction scratch

    const int tid = threadIdx.x;
    const int x0 = blockIdx.x * TX;
    const int y0 = blockIdx.y * TY;
    const int plane = blockIdx.z * (512 * 512);
    const float* pb = pred + plane;
    const float* tb = targ + plane;

    // ---- Load tile with halo, interleave (p,t) into u64 ----
    for (int i = tid; i < LY * LX; i += 256) {
        int r = i / LX;
        int c = i - r * LX;
        int gy = y0 - 5 + r;
        int gx = x0 - 5 + c;
        bool ok = ((unsigned)gy < 512u) && ((unsigned)gx < 512u);
        float pv = ok ? __ldg(pb + gy * 512 + gx) : 0.0f;
        float tv = ok ? __ldg(tb + gy * 512 + gx) : 0.0f;
        spt[r * SPW + c] = pack2(pv, tv);
    }
    __syncthreads();

    // packed weights (duplicated lanes); symmetric -> compiler CSEs to 6 live regs
    u64 wp[11];
    #pragma unroll
    for (int k = 0; k < 11; k++) wp[k] = pack2(GWc(k), GWc(k));

    // ---- Horizontal pass, warp-pure stream assignment ----
    // warps 0-2: stream A (84 tasks)   warps 3-5: stream B (84 tasks)
    // warps 6-7: stream C (42 tasks, row-pairs)
    const int w = tid >> 5;
    if (w < 3) {
        int t = tid;
        if (t < 84) {
            int half = (t >= 42); int r = t - half * 42; int cb = half * 32;
            const u64* row = spt + r * SPW + cb;
            u64 acc[32];
            #pragma unroll
            for (int o = 0; o < 32; o++) acc[o] = 0ull;
            #pragma unroll
            for (int j = 0; j < 42; j++) {
                u64 x = row[j];
                #pragma unroll
                for (int k = 0; k < 11; k++) {
                    int o = j - k;
                    if (o >= 0 && o < 32) acc[o] = fma2(wp[k], x, acc[o]);
                }
            }
            u64* out = shA + r;
            #pragma unroll
            for (int o = 0; o < 32; o++) out[(cb + o) * CS] = acc[o];
        }
    } else if (w < 6) {
        int t = tid - 96;
        if (t < 84) {
            int half = (t >= 42); int r = t - half * 42; int cb = half * 32;
            const u64* row = spt + r * SPW + cb;
            u64 acc[32];
            #pragma unroll
            for (int o = 0; o < 32; o++) acc[o] = 0ull;
            #pragma unroll
            for (int j = 0; j < 42; j++) {
                u64 x = row[j];
                x = mul2(x, x);
                #pragma unroll
                for (int k = 0; k < 11; k++) {
                    int o = j - k;
                    if (o >= 0 && o < 32) acc[o] = fma2(wp[k], x, acc[o]);
                }
            }
            u64* out = shB + r;
            #pragma unroll
            for (int o = 0; o < 32; o++) out[(cb + o) * CS] = acc[o];
        }
    } else {
        int t = tid - 192;
        if (t < 42) {
            int half = (t >= 21); int rp = t - half * 21; int cb = half * 32;
            int r0 = rp, r1 = rp + 21;
            const u64* rowa = spt + r0 * SPW + cb;
            const u64* rowb = spt + r1 * SPW + cb;
            u64 acc[32];
            #pragma unroll
            for (int o = 0; o < 32; o++) acc[o] = 0ull;
            #pragma unroll
            for (int j = 0; j < 42; j++) {
                float pa, ta, pc, tc;
                unpack2(rowa[j], pa, ta);
                unpack2(rowb[j], pc, tc);
                u64 x = pack2(pa * ta, pc * tc);
                #pragma unroll
                for (int k = 0; k < 11; k++) {
                    int o = j - k;
                    if (o >= 0 && o < 32) acc[o] = fma2(wp[k], x, acc[o]);
                }
            }
            #pragma unroll
            for (int o = 0; o < 32; o++) {
                float va, vb;
                unpack2(acc[o], va, vb);
                shC[(cb + o) * CSS + r0] = va;
                shC[(cb + o) * CSS + r1] = vb;
            }
        }
    }
    __syncthreads();

    // ---- Vertical pass + SSIM: thread = (column x, 8-row strip) ----
    const int x  = tid & 63;
    const int r0 = (tid >> 6) * 8;

    u64 mu[8];
    {
        const u64* col = shA + x * CS + r0;
        u64 wv[18];
        #pragma unroll
        for (int j = 0; j < 18; j++) wv[j] = col[j];
        #pragma unroll
        for (int o = 0; o < 8; o++) {
            u64 a = mul2(wp[0], wv[o]);
            #pragma unroll
            for (int k = 1; k < 11; k++) a = fma2(wp[k], wv[o + k], a);
            mu[o] = a;
        }
    }
    u64 sq[8];
    {
        const u64* col = shB + x * CS + r0;
        u64 wv[18];
        #pragma unroll
        for (int j = 0; j < 18; j++) wv[j] = col[j];
        #pragma unroll
        for (int o = 0; o < 8; o++) {
            u64 a = mul2(wp[0], wv[o]);
            #pragma unroll
            for (int k = 1; k < 11; k++) a = fma2(wp[k], wv[o + k], a);
            sq[o] = a;
        }
    }
    float cpt[8];
    {
        const float* col = shC + x * CSS + r0;
        float wc[18];
        #pragma unroll
        for (int j = 0; j < 18; j++) wc[j] = col[j];
        u64 pw[14];
        #pragma unroll
        for (int j = 0; j < 14; j++) pw[j] = pack2(wc[j], wc[j + 4]);
        #pragma unroll
        for (int o = 0; o < 4; o++) {
            u64 a = mul2(wp[0], pw[o]);
            #pragma unroll
            for (int k = 1; k < 11; k++) a = fma2(wp[k], pw[o + k], a);
            unpack2(a, cpt[o], cpt[o + 4]);   // outputs o and o+4
        }
    }

    const float C1 = 0.0001f;
    const float C2 = 0.0009f;
    float lsum = 0.0f;
    #pragma unroll
    for (int o = 0; o < 8; o++) {
        float mu1, mu2, ep2, et2;
        unpack2(mu[o], mu1, mu2);
        unpack2(sq[o], ep2, et2);
        float mu1sq = mu1 * mu1;
        float mu2sq = mu2 * mu2;
        float mu12  = mu1 * mu2;
        float s1  = ep2 - mu1sq;
        float s2  = et2 - mu2sq;
        float s12 = cpt[o] - mu12;
        float num = (2.0f * mu12 + C1) * (2.0f * s12 + C2);
        float den = (mu1sq + mu2sq + C1) * (s1 + s2 + C2);
        lsum += __fdividef(num, den);
    }

    // ---- Deterministic block reduction ----
    #pragma unroll
    for (int off = 16; off > 0; off >>= 1)
        lsum += __shfl_down_sync(0xffffffffu, lsum, off);
    if ((tid & 31) == 0) sred[tid >> 5] = lsum;
    __syncthreads();
    if (tid == 0) {
        float tot = 0.0f;
        #pragma unroll
        for (int wi = 0; wi < 8; wi++) tot += sred[wi];
        int bidx = (blockIdx.z * gridDim.y + blockIdx.y) * gridDim.x + blockIdx.x;
        g_partials[bidx] = tot;
    }
}

__global__ void __launch_bounds__(1024, 1)
ssim_finalize(float* __restrict__ out)
{
    __shared__ double shr[32];
    const int tid = threadIdx.x;
    double s = 0.0;
    for (int i = tid; i < NBLK; i += 1024)
        s += (double)g_partials[i];
    #pragma unroll
    for (int off = 16; off > 0; off >>= 1)
        s += __shfl_down_sync(0xffffffffu, s, off);
    if ((tid & 31) == 0) shr[tid >> 5] = s;
    __syncthreads();
    if (tid == 0) {
        double tot = 0.0;
        #pragma unroll
        for (int w = 0; w < 32; w++) tot += shr[w];
        out[0] = (float)(1.0 - tot / NTOT);
    }
}

extern "C" void kernel_launch(void* const* d_in, const int* in_sizes, int n_in,
                              void* d_out, int out_size)
{
    const float* pred = (const float*)d_in[0];
    const float* targ = (const float*)d_in[1];
    float* out = (float*)d_out;

    constexpr int smem_bytes =
        (LY * SPW + 2 * 64 * CS) * 8 + 64 * CSS * 4 + 8 * 4;
    cudaFuncSetAttribute(ssim_tile_kernel,
                         cudaFuncAttributeMaxDynamicSharedMemorySize, smem_bytes);

    dim3 grid(GX, GY, GZ);
    ssim_tile_kernel<<<grid, 256, smem_bytes>>>(pred, targ);
    ssim_finalize<<<1, 1024>>>(out);
}

// round 11
// speedup vs baseline: 1.1839x; 1.1827x over previous
#include <cuda_runtime.h>

// SSIM loss, pred/target [16,3,512,512] f32.
// Vertical-first separable 11-tap Gaussian, f32x2-packed:
//   stream A: (p, t) packed      stream B: (p*p, t*t) packed   stream C: p*t scalar
// Phase1: gmem -> smem (p,t) packed tile (74x42)
// Phase2: vertical conv, sliding 11-reg window, -> vA/vB/vC [col][row] in smem
// Phase3: horizontal conv + SSIM map + deterministic block reduce
// Tile grid split into 3 z-chunks so ncu (-s 5) captures a tile launch.

#define TX   64
#define TY   32
#define LX   74
#define LY   42
#define SPW  75      // input tile row stride (u64)
#define CS   33      // v* column stride (32 rows + 1 pad)
#define GX   (512/TX)
#define GY   (512/TY)
#define GZC  16      // z per chunk (3 chunks x 16 = 48 planes)
#define NBLK (GX*GY*48)
#define NTOT 12582912.0

using u64 = unsigned long long;

__host__ __device__ constexpr float GWc(int k) {
    return (k == 0) ? 0.00102838f
         : (k == 1) ? 0.00759875f
         : (k == 2) ? 0.03600077f
         : (k == 3) ? 0.10936070f
         : (k == 4) ? 0.21300553f
         : (k == 5) ? 0.26601172f
         : (k == 6) ? 0.21300553f
         : (k == 7) ? 0.10936070f
         : (k == 8) ? 0.03600077f
         : (k == 9) ? 0.00759875f
         :            0.00102838f;
}

__device__ __forceinline__ u64 pack2(float lo, float hi) {
    u64 r; asm("mov.b64 %0, {%1,%2};" : "=l"(r) : "f"(lo), "f"(hi)); return r;
}
__device__ __forceinline__ void unpack2(u64 v, float& lo, float& hi) {
    asm("mov.b64 {%0,%1}, %2;" : "=f"(lo), "=f"(hi) : "l"(v));
}
__device__ __forceinline__ u64 fma2(u64 a, u64 b, u64 c) {
    u64 r; asm("fma.rn.f32x2 %0, %1, %2, %3;" : "=l"(r) : "l"(a), "l"(b), "l"(c)); return r;
}
__device__ __forceinline__ u64 mul2(u64 a, u64 b) {
    u64 r; asm("mul.rn.f32x2 %0, %1, %2;" : "=l"(r) : "l"(a), "l"(b)); return r;
}

__device__ float g_partials[NBLK];

__global__ void __launch_bounds__(256, 2)
ssim_tile_kernel(const float* __restrict__ pred, const float* __restrict__ targ,
                 int zbase)
{
    extern __shared__ char smem_raw[];
    u64*   spt  = (u64*)smem_raw;              // LY*SPW   (p,t) tile
    u64*   vA   = spt + LY * SPW;              // 74*CS    vpass (mu1v, mu2v) [col][row]
    u64*   vB   = vA + 74 * CS;                // 74*CS    vpass (p2v, t2v)   [col][row]
    float* vC   = (float*)(vB + 74 * CS);      // 74*CS    vpass ptv          [col][row]
    float* sred = vC + 74 * CS;                // 8 floats

    const int tid = threadIdx.x;
    const int x0 = blockIdx.x * TX;
    const int y0 = blockIdx.y * TY;
    const int z  = zbase + blockIdx.z;
    const float* pb = pred + z * (512 * 512);
    const float* tb = targ + z * (512 * 512);

    // ---- Phase 1: load tile with halo, interleave (p,t) ----
    for (int i = tid; i < LY * LX; i += 256) {
        int r = i / LX;
        int c = i - r * LX;
        int gy = y0 - 5 + r;
        int gx = x0 - 5 + c;
        bool ok = ((unsigned)gy < 512u) && ((unsigned)gx < 512u);
        float pv = ok ? __ldg(pb + gy * 512 + gx) : 0.0f;
        float tv = ok ? __ldg(tb + gy * 512 + gx) : 0.0f;
        spt[r * SPW + c] = pack2(pv, tv);
    }
    __syncthreads();

    // ---- Phase 2: vertical conv, one column per thread, sliding window ----
    // A: tids 0-73, B: 80-153, C: 160-233 (warp-pure except warp 2: A+B)
    if (tid < 74) {
        const int c = tid;
        const u64* in = spt + c;
        u64 win[11];
        #pragma unroll
        for (int j = 0; j < 10; j++) win[j] = in[j * SPW];
        u64* out = vA + c * CS;
        #pragma unroll
        for (int r = 0; r < 32; r++) {
            win[10] = in[(r + 10) * SPW];
            u64 a = mul2(pack2(GWc(0), GWc(0)), win[0]);
            #pragma unroll
            for (int k = 1; k < 11; k++)
                a = fma2(pack2(GWc(k), GWc(k)), win[k], a);
            out[r] = a;
            #pragma unroll
            for (int j = 0; j < 10; j++) win[j] = win[j + 1];
        }
    } else if (tid >= 80 && tid < 154) {
        const int c = tid - 80;
        const u64* in = spt + c;
        u64 win[11];
        #pragma unroll
        for (int j = 0; j < 10; j++) { u64 v = in[j * SPW]; win[j] = mul2(v, v); }
        u64* out = vB + c * CS;
        #pragma unroll
        for (int r = 0; r < 32; r++) {
            u64 v = in[(r + 10) * SPW];
            win[10] = mul2(v, v);
            u64 a = mul2(pack2(GWc(0), GWc(0)), win[0]);
            #pragma unroll
            for (int k = 1; k < 11; k++)
                a = fma2(pack2(GWc(k), GWc(k)), win[k], a);
            out[r] = a;
            #pragma unroll
            for (int j = 0; j < 10; j++) win[j] = win[j + 1];
        }
    } else if (tid >= 160 && tid < 234) {
        const int c = tid - 160;
        const u64* in = spt + c;
        float win[11];
        #pragma unroll
        for (int j = 0; j < 10; j++) {
            float p, t; unpack2(in[j * SPW], p, t); win[j] = p * t;
        }
        float* out = vC + c * CS;
        #pragma unroll
        for (int r = 0; r < 32; r++) {
            float p, t; unpack2(in[(r + 10) * SPW], p, t);
            win[10] = p * t;
            float a = GWc(0) * win[0];
            #pragma unroll
            for (int k = 1; k < 11; k++) a = fmaf(GWc(k), win[k], a);
            out[r] = a;
            #pragma unroll
            for (int j = 0; j < 10; j++) win[j] = win[j + 1];
        }
    }
    __syncthreads();

    // ---- Phase 3: horizontal conv + SSIM. warp = 32 rows, one x-group ----
    const int g = tid >> 5;     // x-group 0..7, outputs x = 8g..8g+7
    const int r = tid & 31;     // row

    u64 mu[8];
    {
        const u64* base = vA + (8 * g) * CS + r;
        u64 wv[18];
        #pragma unroll
        for (int j = 0; j < 18; j++) wv[j] = base[j * CS];
        #pragma unroll
        for (int o = 0; o < 8; o++) {
            u64 a = mul2(pack2(GWc(0), GWc(0)), wv[o]);
            #pragma unroll
            for (int k = 1; k < 11; k++)
                a = fma2(pack2(GWc(k), GWc(k)), wv[o + k], a);
            mu[o] = a;
        }
    }
    u64 sq[8];
    {
        const u64* base = vB + (8 * g) * CS + r;
        u64 wv[18];
        #pragma unroll
        for (int j = 0; j < 18; j++) wv[j] = base[j * CS];
        #pragma unroll
        for (int o = 0; o < 8; o++) {
            u64 a = mul2(pack2(GWc(0), GWc(0)), wv[o]);
            #pragma unroll
            for (int k = 1; k < 11; k++)
                a = fma2(pack2(GWc(k), GWc(k)), wv[o + k], a);
            sq[o] = a;
        }
    }
    float cpt[8];
    {
        const float* base = vC + (8 * g) * CS + r;
        float wc[18];
        #pragma unroll
        for (int j = 0; j < 18; j++) wc[j] = base[j * CS];
        u64 pw[14];
        #pragma unroll
        for (int j = 0; j < 14; j++) pw[j] = pack2(wc[j], wc[j + 4]);
        #pragma unroll
        for (int o = 0; o < 4; o++) {
            u64 a = mul2(pack2(GWc(0), GWc(0)), pw[o]);
            #pragma unroll
            for (int k = 1; k < 11; k++)
                a = fma2(pack2(GWc(k), GWc(k)), pw[o + k], a);
            unpack2(a, cpt[o], cpt[o + 4]);
        }
    }

    const float C1 = 0.0001f;
    const float C2 = 0.0009f;
    float lsum = 0.0f;
    #pragma unroll
    for (int o = 0; o < 8; o++) {
        float mu1, mu2, ep2, et2;
        unpack2(mu[o], mu1, mu2);
        unpack2(sq[o], ep2, et2);
        float mu1sq = mu1 * mu1;
        float mu2sq = mu2 * mu2;
        float mu12  = mu1 * mu2;
        float s1  = ep2 - mu1sq;
        float s2  = et2 - mu2sq;
        float s12 = cpt[o] - mu12;
        float num = (2.0f * mu12 + C1) * (2.0f * s12 + C2);
        float den = (mu1sq + mu2sq + C1) * (s1 + s2 + C2);
        lsum += __fdividef(num, den);
    }

    // ---- Deterministic block reduction ----
    #pragma unroll
    for (int off = 16; off > 0; off >>= 1)
        lsum += __shfl_down_sync(0xffffffffu, lsum, off);
    if ((tid & 31) == 0) sred[tid >> 5] = lsum;
    __syncthreads();
    if (tid == 0) {
        float tot = 0.0f;
        #pragma unroll
        for (int wi = 0; wi < 8; wi++) tot += sred[wi];
        int bidx = ((z)*gridDim.y + blockIdx.y) * gridDim.x + blockIdx.x;
        g_partials[bidx] = tot;
    }
}

__global__ void __launch_bounds__(1024, 1)
ssim_finalize(float* __restrict__ out)
{
    __shared__ double shr[32];
    const int tid = threadIdx.x;
    double s = 0.0;
    for (int i = tid; i < NBLK; i += 1024)
        s += (double)g_partials[i];
    #pragma unroll
    for (int off = 16; off > 0; off >>= 1)
        s += __shfl_down_sync(0xffffffffu, s, off);
    if ((tid & 31) == 0) shr[tid >> 5] = s;
    __syncthreads();
    if (tid == 0) {
        double tot = 0.0;
        #pragma unroll
        for (int w = 0; w < 32; w++) tot += shr[w];
        out[0] = (float)(1.0 - tot / NTOT);
    }
}

extern "C" void kernel_launch(void* const* d_in, const int* in_sizes, int n_in,
                              void* d_out, int out_size)
{
    const float* pred = (const float*)d_in[0];
    const float* targ = (const float*)d_in[1];
    float* out = (float*)d_out;

    constexpr int smem_bytes =
        (LY * SPW + 2 * 74 * CS) * 8 + 74 * CS * 4 + 8 * 4;
    cudaFuncSetAttribute(ssim_tile_kernel,
                         cudaFuncAttributeMaxDynamicSharedMemorySize, smem_bytes);

    dim3 grid(GX, GY, GZC);
    // 3 z-chunks: 4 launches per call so ncu -s 5 lands on a tile launch.
    ssim_tile_kernel<<<grid, 256, smem_bytes>>>(pred, targ, 0);
    ssim_tile_kernel<<<grid, 256, smem_bytes>>>(pred, targ, 16);
    ssim_tile_kernel<<<grid, 256, smem_bytes>>>(pred, targ, 32);
    ssim_finalize<<<1, 1024>>>(out);
}

// round 12
// speedup vs baseline: 1.3048x; 1.1021x over previous
#include <cuda_runtime.h>

// SSIM loss, pred/target [16,3,512,512] f32.
// Vertical-first separable 11-tap Gaussian, f32x2-packed:
//   stream A: (p, t) packed   stream B: (p*p, t*t) packed   stream C: p*t scalar
// Phase1: gmem -> smem (p,t) packed tile (74x42)
// Phase2: vertical conv, modulo-rotation register windows; A+B fused (shared
//         loads), tasks=(col,half) on tids 0-147; C on tids 160-233.
// Phase3: horizontal conv + SSIM map + deterministic block reduce
// Finalize folded into last-finished block (atomic counter, fixed-order sum).

#define TX   64
#define TY   32
#define LX   74
#define LY   42
#define SPW  75      // input tile row stride (u64)
#define CS   33      // v* column stride (32 rows + 1 pad)
#define GX   (512/TX)
#define GY   (512/TY)
#define GZ   48
#define NBLK (GX*GY*GZ)
#define NTOT 12582912.0

using u64 = unsigned long long;

__host__ __device__ constexpr float GWc(int k) {
    return (k == 0) ? 0.00102838f
         : (k == 1) ? 0.00759875f
         : (k == 2) ? 0.03600077f
         : (k == 3) ? 0.10936070f
         : (k == 4) ? 0.21300553f
         : (k == 5) ? 0.26601172f
         : (k == 6) ? 0.21300553f
         : (k == 7) ? 0.10936070f
         : (k == 8) ? 0.03600077f
         : (k == 9) ? 0.00759875f
         :            0.00102838f;
}

__device__ __forceinline__ u64 pack2(float lo, float hi) {
    u64 r; asm("mov.b64 %0, {%1,%2};" : "=l"(r) : "f"(lo), "f"(hi)); return r;
}
__device__ __forceinline__ void unpack2(u64 v, float& lo, float& hi) {
    asm("mov.b64 {%0,%1}, %2;" : "=f"(lo), "=f"(hi) : "l"(v));
}
__device__ __forceinline__ u64 fma2(u64 a, u64 b, u64 c) {
    u64 r; asm("fma.rn.f32x2 %0, %1, %2, %3;" : "=l"(r) : "l"(a), "l"(b), "l"(c)); return r;
}
__device__ __forceinline__ u64 mul2(u64 a, u64 b) {
    u64 r; asm("mul.rn.f32x2 %0, %1, %2;" : "=l"(r) : "l"(a), "l"(b)); return r;
}

__device__ float g_partials[NBLK];
__device__ unsigned int g_count = 0;

__global__ void __launch_bounds__(256, 2)
ssim_tile_kernel(const float* __restrict__ pred, const float* __restrict__ targ,
                 float* __restrict__ out)
{
    extern __shared__ char smem_raw[];
    u64*   spt  = (u64*)smem_raw;              // LY*SPW   (p,t) tile
    u64*   vA   = spt + LY * SPW;              // 74*CS    vpass (mu1v, mu2v) [col][row]
    u64*   vB   = vA + 74 * CS;                // 74*CS    vpass (p2v, t2v)   [col][row]
    float* vC   = (float*)(vB + 74 * CS);      // 74*CS    vpass ptv          [col][row]
    float* sred = vC + 74 * CS;                // 8 floats

    const int tid = threadIdx.x;
    const int x0 = blockIdx.x * TX;
    const int y0 = blockIdx.y * TY;
    const int z  = blockIdx.z;
    const float* pb = pred + z * (512 * 512);
    const float* tb = targ + z * (512 * 512);

    // ---- Phase 1: load tile with halo, interleave (p,t) ----
    for (int i = tid; i < LY * LX; i += 256) {
        int r = i / LX;
        int c = i - r * LX;
        int gy = y0 - 5 + r;
        int gx = x0 - 5 + c;
        bool ok = ((unsigned)gy < 512u) && ((unsigned)gx < 512u);
        float pv = ok ? __ldg(pb + gy * 512 + gx) : 0.0f;
        float tv = ok ? __ldg(tb + gy * 512 + gx) : 0.0f;
        spt[r * SPW + c] = pack2(pv, tv);
    }
    __syncthreads();

    // ---- Phase 2: vertical conv, modulo-rotation windows ----
    // A+B fused (shared loads): tids 0-147, task = (col, 16-row half).
    // C (p*t scalar): tids 160-233, one full column each.
    if (tid < 148) {
        const int h = (tid >= 74);            // row half
        const int c = tid - h * 74;           // column
        const int rb = h * 16;                // first output row
        const u64* in = spt + c;
        u64 winA[11], winB[11];
        #pragma unroll
        for (int j = 0; j < 10; j++) {
            u64 v = in[(rb + j) * SPW];
            winA[j] = v;
            winB[j] = mul2(v, v);
        }
        u64* oA = vA + c * CS + rb;
        u64* oB = vB + c * CS + rb;
        #pragma unroll
        for (int r = 0; r < 16; r++) {
            u64 v = in[(rb + r + 10) * SPW];
            winA[(r + 10) % 11] = v;
            winB[(r + 10) % 11] = mul2(v, v);
            u64 a = mul2(pack2(GWc(0), GWc(0)), winA[r % 11]);
            u64 b = mul2(pack2(GWc(0), GWc(0)), winB[r % 11]);
            #pragma unroll
            for (int k = 1; k < 11; k++) {
                a = fma2(pack2(GWc(k), GWc(k)), winA[(r + k) % 11], a);
                b = fma2(pack2(GWc(k), GWc(k)), winB[(r + k) % 11], b);
            }
            oA[r] = a;
            oB[r] = b;
        }
    } else if (tid >= 160 && tid < 234) {
        const int c = tid - 160;
        const u64* in = spt + c;
        float win[11];
        #pragma unroll
        for (int j = 0; j < 10; j++) {
            float p, t; unpack2(in[j * SPW], p, t);
            win[j] = p * t;
        }
        float* oC = vC + c * CS;
        #pragma unroll
        for (int r = 0; r < 32; r++) {
            float p, t; unpack2(in[(r + 10) * SPW], p, t);
            win[(r + 10) % 11] = p * t;
            float a = GWc(0) * win[r % 11];
            #pragma unroll
            for (int k = 1; k < 11; k++) a = fmaf(GWc(k), win[(r + k) % 11], a);
            oC[r] = a;
        }
    }
    __syncthreads();

    // ---- Phase 3: horizontal conv + SSIM. warp = 32 rows, one x-group ----
    const int g = tid >> 5;     // x-group 0..7, outputs x = 8g..8g+7
    const int r = tid & 31;     // row

    u64 mu[8];
    {
        const u64* base = vA + (8 * g) * CS + r;
        u64 wv[18];
        #pragma unroll
        for (int j = 0; j < 18; j++) wv[j] = base[j * CS];
        #pragma unroll
        for (int o = 0; o < 8; o++) {
            u64 a = mul2(pack2(GWc(0), GWc(0)), wv[o]);
            #pragma unroll
            for (int k = 1; k < 11; k++)
                a = fma2(pack2(GWc(k), GWc(k)), wv[o + k], a);
            mu[o] = a;
        }
    }
    u64 sq[8];
    {
        const u64* base = vB + (8 * g) * CS + r;
        u64 wv[18];
        #pragma unroll
        for (int j = 0; j < 18; j++) wv[j] = base[j * CS];
        #pragma unroll
        for (int o = 0; o < 8; o++) {
            u64 a = mul2(pack2(GWc(0), GWc(0)), wv[o]);
            #pragma unroll
            for (int k = 1; k < 11; k++)
                a = fma2(pack2(GWc(k), GWc(k)), wv[o + k], a);
            sq[o] = a;
        }
    }
    float cpt[8];
    {
        const float* base = vC + (8 * g) * CS + r;
        float wc[18];
        #pragma unroll
        for (int j = 0; j < 18; j++) wc[j] = base[j * CS];
        u64 pw[14];
        #pragma unroll
        for (int j = 0; j < 14; j++) pw[j] = pack2(wc[j], wc[j + 4]);
        #pragma unroll
        for (int o = 0; o < 4; o++) {
            u64 a = mul2(pack2(GWc(0), GWc(0)), pw[o]);
            #pragma unroll
            for (int k = 1; k < 11; k++)
                a = fma2(pack2(GWc(k), GWc(k)), pw[o + k], a);
            unpack2(a, cpt[o], cpt[o + 4]);
        }
    }

    const float C1 = 0.0001f;
    const float C2 = 0.0009f;
    float lsum = 0.0f;
    #pragma unroll
    for (int o = 0; o < 8; o++) {
        float mu1, mu2, ep2, et2;
        unpack2(mu[o], mu1, mu2);
        unpack2(sq[o], ep2, et2);
        float mu1sq = mu1 * mu1;
        float mu2sq = mu2 * mu2;
        float mu12  = mu1 * mu2;
        float s1  = ep2 - mu1sq;
        float s2  = et2 - mu2sq;
        float s12 = cpt[o] - mu12;
        float num = (2.0f * mu12 + C1) * (2.0f * s12 + C2);
        float den = (mu1sq + mu2sq + C1) * (s1 + s2 + C2);
        lsum += __fdividef(num, den);
    }

    // ---- Deterministic block reduction ----
    #pragma unroll
    for (int off = 16; off > 0; off >>= 1)
        lsum += __shfl_down_sync(0xffffffffu, lsum, off);
    if ((tid & 31) == 0) sred[tid >> 5] = lsum;
    __syncthreads();

    __shared__ bool s_last;
    if (tid == 0) {
        float tot = 0.0f;
        #pragma unroll
        for (int wi = 0; wi < 8; wi++) tot += sred[wi];
        int bidx = (z * gridDim.y + blockIdx.y) * gridDim.x + blockIdx.x;
        g_partials[bidx] = tot;
        __threadfence();
        unsigned v = atomicAdd(&g_count, 1u);
        s_last = (v == (unsigned)(NBLK - 1));
    }
    __syncthreads();

    // ---- Last block finalizes (deterministic fixed-order sum) ----
    if (s_last) {
        __threadfence();
        double* dred = (double*)smem_raw;  // spt region is dead
        double s = 0.0;
        for (int i = tid; i < NBLK; i += 256)
            s += (double)g_partials[i];
        #pragma unroll
        for (int off = 16; off > 0; off >>= 1)
            s += __shfl_down_sync(0xffffffffu, s, off);
        if ((tid & 31) == 0) dred[tid >> 5] = s;
        __syncthreads();
        if (tid == 0) {
            double tot = 0.0;
            #pragma unroll
            for (int w = 0; w < 8; w++) tot += dred[w];
            out[0] = (float)(1.0 - tot / NTOT);
            g_count = 0;   // reset for next graph replay
        }
    }
}

extern "C" void kernel_launch(void* const* d_in, const int* in_sizes, int n_in,
                              void* d_out, int out_size)
{
    const float* pred = (const float*)d_in[0];
    const float* targ = (const float*)d_in[1];
    float* out = (float*)d_out;

    constexpr int smem_bytes =
        (LY * SPW + 2 * 74 * CS) * 8 + 74 * CS * 4 + 16 * 4;
    cudaFuncSetAttribute(ssim_tile_kernel,
                         cudaFuncAttributeMaxDynamicSharedMemorySize, smem_bytes);

    dim3 grid(GX, GY, GZ);
    ssim_tile_kernel<<<grid, 256, smem_bytes>>>(pred, targ, out);
}